// round 3
// baseline (speedup 1.0000x reference)
#include <cuda_runtime.h>
#include <cstdint>

#define N_PTS      16384
#define B_SZ       4
#define S_SAMPLES  1024
#define K_NB       32
#define C_FEAT     128

#define CEN_OFF    0
#define GX_OFF     (B_SZ * S_SAMPLES * 3)                      // 12288
#define GF_OFF     (GX_OFF + B_SZ * S_SAMPLES * K_NB * 3)     // 405504

#define FPS_T      512
#define PPT        32                   // points per thread
#define FPAIRS     16                   // PPT/2 packed pairs
#define N_CELLS    512                  // 8x8x8 spatial grid

typedef unsigned long long ull;

// ---------------- packed f32x2 helpers (exact per-lane round-to-nearest) ----
__device__ __forceinline__ ull pack2(float lo, float hi) {
    ull r; asm("mov.b64 %0, {%1, %2};" : "=l"(r) : "f"(lo), "f"(hi)); return r;
}
__device__ __forceinline__ void unpack2(ull v, float& lo, float& hi) {
    asm("mov.b64 {%0, %1}, %2;" : "=f"(lo), "=f"(hi) : "l"(v));
}
__device__ __forceinline__ ull addx2(ull a, ull b) {
    ull r; asm("add.rn.f32x2 %0, %1, %2;" : "=l"(r) : "l"(a), "l"(b)); return r;
}
__device__ __forceinline__ ull mulx2(ull a, ull b) {
    ull r; asm("mul.rn.f32x2 %0, %1, %2;" : "=l"(r) : "l"(a), "l"(b)); return r;
}

// ---------------- spatially sorted scratch (device globals: no allocs) ------
__device__ float g_sx[B_SZ * N_PTS];
__device__ float g_sy[B_SZ * N_PTS];
__device__ float g_sz[B_SZ * N_PTS];
__device__ int   g_sid[B_SZ * N_PTS];

__device__ __forceinline__ int cell_of(float x, float y, float z) {
    int cx = min(max((int)(x * 8.0f), 0), 7);
    int cy = min(max((int)(y * 8.0f), 0), 7);
    int cz = min(max((int)(z * 8.0f), 0), 7);
    return (cx << 6) | (cy << 3) | cz;
}

// ============================================================================
// Counting sort by 8x8x8 cell. One CTA per batch. Scatter order inside a cell
// is nondeterministic (atomics) but the FPS output is provably independent of
// point order (order-free min updates + order-free 64-bit argmax keys).
// ============================================================================
__global__ __launch_bounds__(N_CELLS)
void sort_kernel(const float* __restrict__ xyz)
{
    __shared__ int hist[N_CELLS];
    const int t = threadIdx.x;
    const int b = blockIdx.x;
    const float* base = xyz + (size_t)b * N_PTS * 3;

    hist[t] = 0;
    __syncthreads();
    for (int i = t; i < N_PTS; i += N_CELLS) {
        atomicAdd(&hist[cell_of(base[3 * i], base[3 * i + 1], base[3 * i + 2])], 1);
    }
    __syncthreads();
    // inclusive Hillis-Steele scan over 512 cells, then make exclusive
    const int cnt0 = hist[t];
#pragma unroll
    for (int d = 1; d < N_CELLS; d <<= 1) {
        int add = (t >= d) ? hist[t - d] : 0;
        __syncthreads();
        hist[t] += add;
        __syncthreads();
    }
    hist[t] -= cnt0;            // exclusive offsets
    __syncthreads();
    for (int i = t; i < N_PTS; i += N_CELLS) {
        const float x = base[3 * i], y = base[3 * i + 1], z = base[3 * i + 2];
        const int pos = atomicAdd(&hist[cell_of(x, y, z)], 1);
        const int o = b * N_PTS + pos;
        g_sx[o] = x; g_sy[o] = y; g_sz[o] = z; g_sid[o] = i;
    }
}

// ============================================================================
// FPS with exact bounding-box pruning. One CTA per batch, 512 threads, each
// owning 32 spatially-contiguous sorted points. min_d in registers.
//   skip thread iff  0.99999 * lb2_rd(centroid, threadBB)  >=  thread_vmax
// (round-down bound; skipped updates provably cannot change any min_d).
// Argmax key = (float_bits(vmax)<<32) | (0xFFFFFFFF - orig_idx): max key ==
// (max value, first-occurrence index) regardless of scan order.
// ============================================================================
__global__ __launch_bounds__(FPS_T, 1)
void fps_kernel(const float* __restrict__ xyz, float* __restrict__ out)
{
    __shared__ ull   s_wkey[16];
    __shared__ ull   s_gkey;
    __shared__ float s_cx, s_cy, s_cz;

    const int t = threadIdx.x;
    const int b = blockIdx.x;
    const int lane = t & 31, w = t >> 5;
    const int pb = b * N_PTS + t * PPT;
    float* cen = out + CEN_OFF + (size_t)b * S_SAMPLES * 3;

    ull X[FPAIRS], Y[FPAIRS], Z[FPAIRS];
    float M[PPT];
    int ID[PPT];
    float blx = 1e30f, bly = 1e30f, blz = 1e30f;
    float bhx = -1e30f, bhy = -1e30f, bhz = -1e30f;
#pragma unroll
    for (int q = 0; q < FPAIRS; ++q) {
        const int i0 = pb + 2 * q, i1 = i0 + 1;
        const float x0 = g_sx[i0], x1 = g_sx[i1];
        const float y0 = g_sy[i0], y1 = g_sy[i1];
        const float z0 = g_sz[i0], z1 = g_sz[i1];
        X[q] = pack2(x0, x1); Y[q] = pack2(y0, y1); Z[q] = pack2(z0, z1);
        ID[2 * q] = g_sid[i0]; ID[2 * q + 1] = g_sid[i1];
        M[2 * q] = 1e10f; M[2 * q + 1] = 1e10f;
        blx = fminf(blx, fminf(x0, x1)); bhx = fmaxf(bhx, fmaxf(x0, x1));
        bly = fminf(bly, fminf(y0, y1)); bhy = fmaxf(bhy, fmaxf(y0, y1));
        blz = fminf(blz, fminf(z0, z1)); bhz = fmaxf(bhz, fmaxf(z0, z1));
    }

    float vmax = 1e10f;     // forces full update on first iteration
    ull ckey = 0;

    const float* obase = xyz + (size_t)b * N_PTS * 3;
    float cx = __ldg(obase + 0), cy = __ldg(obase + 1), cz = __ldg(obase + 2);
    if (t == 0) { cen[0] = cx; cen[1] = cy; cen[2] = cz; }

    for (int s = 1; s < S_SAMPLES; ++s) {
        // ---- conservative lower bound on dist^2(centroid, thread BB) ----
        const float dx = fmaxf(fmaxf(__fsub_rd(blx, cx), __fsub_rd(cx, bhx)), 0.0f);
        const float dy = fmaxf(fmaxf(__fsub_rd(bly, cy), __fsub_rd(cy, bhy)), 0.0f);
        const float dz = fmaxf(fmaxf(__fsub_rd(blz, cz), __fsub_rd(cz, bhz)), 0.0f);
        const float lb2 = __fadd_rd(__fadd_rd(__fmul_rd(dx, dx), __fmul_rd(dy, dy)),
                                    __fmul_rd(dz, dz));
        const float lb2s = __fmul_rd(lb2, 0.99999f);

        if (lb2s < vmax) {
            const ull nx = pack2(-cx, -cx);
            const ull ny = pack2(-cy, -cy);
            const ull nz = pack2(-cz, -cz);
#pragma unroll
            for (int q = 0; q < FPAIRS; ++q) {
                ull ddx = addx2(X[q], nx);                 // rn(x - cx)
                ull ddy = addx2(Y[q], ny);
                ull ddz = addx2(Z[q], nz);
                ull d2 = addx2(addx2(mulx2(ddx, ddx), mulx2(ddy, ddy)),
                               mulx2(ddz, ddz));
                float d0, d1; unpack2(d2, d0, d1);
                M[2 * q]     = fminf(M[2 * q],     d0);
                M[2 * q + 1] = fminf(M[2 * q + 1], d1);
            }
            // thread max (4-way tree to shorten dep chain)
            float a0 = -1.f, a1 = -1.f, a2 = -1.f, a3 = -1.f;
#pragma unroll
            for (int i = 0; i < PPT; i += 4) {
                a0 = fmaxf(a0, M[i]);     a1 = fmaxf(a1, M[i + 1]);
                a2 = fmaxf(a2, M[i + 2]); a3 = fmaxf(a3, M[i + 3]);
            }
            vmax = fmaxf(fmaxf(a0, a1), fmaxf(a2, a3));
            // first-occurrence (min orig idx) among points equal to vmax
            int best = 0x7FFFFFFF;
#pragma unroll
            for (int i = 0; i < PPT; ++i)
                if (M[i] == vmax) best = min(best, ID[i]);
            ckey = ((ull)__float_as_uint(vmax) << 32)
                 | (unsigned)(0xFFFFFFFFu - (unsigned)best);
        }

        // ---- CTA argmax reduction over 64-bit keys ----
        ull key = ckey;
#pragma unroll
        for (int off = 16; off > 0; off >>= 1) {
            ull o = __shfl_down_sync(0xFFFFFFFFu, key, off);
            if (o > key) key = o;
        }
        if (lane == 0) s_wkey[w] = key;
        __syncthreads();
        if (w == 0) {
            ull k2 = (lane < 16) ? s_wkey[lane] : 0ull;
#pragma unroll
            for (int off = 8; off > 0; off >>= 1) {
                ull o = __shfl_down_sync(0xFFFFFFFFu, k2, off);
                if (o > k2) k2 = o;
            }
            if (lane == 0) s_gkey = k2;
        }
        __syncthreads();
        const ull gk = s_gkey;

        // ---- unique winner thread publishes the new centroid coords ----
        if (ckey == gk) {
            const unsigned target = 0xFFFFFFFFu - (unsigned)gk;
#pragma unroll
            for (int q = 0; q < FPAIRS; ++q) {
                float x0, x1, y0, y1, z0, z1;
                unpack2(X[q], x0, x1); unpack2(Y[q], y0, y1); unpack2(Z[q], z0, z1);
                if ((unsigned)ID[2 * q] == target)     { s_cx = x0; s_cy = y0; s_cz = z0; }
                if ((unsigned)ID[2 * q + 1] == target) { s_cx = x1; s_cy = y1; s_cz = z1; }
            }
        }
        __syncthreads();
        cx = s_cx; cy = s_cy; cz = s_cz;
        if (t == 0) { cen[s * 3 + 0] = cx; cen[s * 3 + 1] = cy; cen[s * 3 + 2] = cz; }
    }
}

// ============================================================================
// Ball query + gather: one warp per centroid, 64 points per ballot iteration,
// early exit at K hits. Scan order == ascending index == reference top_k order.
// ============================================================================
#define BQ_WARPS 8

__global__ __launch_bounds__(BQ_WARPS * 32)
void group_kernel(const float* __restrict__ xyz,
                  const float* __restrict__ feat,
                  float* __restrict__ out)
{
    const int w    = threadIdx.x >> 5;
    const int lane = threadIdx.x & 31;
    const int c    = blockIdx.x * BQ_WARPS + w;          // centroid id
    const int b    = c >> 10;
    const float* base = xyz + (size_t)b * N_PTS * 3;

    const float* cen = out + CEN_OFF + (size_t)c * 3;
    const float cx = __ldg(cen + 0), cy = __ldg(cen + 1), cz = __ldg(cen + 2);
    const float R2 = (float)(0.2 * 0.2);

    __shared__ int s_idx[BQ_WARPS][K_NB];

    int cnt = 0;
    for (int j = 0; j < N_PTS / 64 && cnt < K_NB; ++j) {
        const int p0 = j * 64 + lane;
        const int p1 = p0 + 32;
        const float dx0 = __fadd_rn(cx, -base[p0 * 3 + 0]);
        const float dy0 = __fadd_rn(cy, -base[p0 * 3 + 1]);
        const float dz0 = __fadd_rn(cz, -base[p0 * 3 + 2]);
        const float sq0 = __fadd_rn(__fadd_rn(__fmul_rn(dx0, dx0), __fmul_rn(dy0, dy0)),
                                    __fmul_rn(dz0, dz0));
        const float dx1 = __fadd_rn(cx, -base[p1 * 3 + 0]);
        const float dy1 = __fadd_rn(cy, -base[p1 * 3 + 1]);
        const float dz1 = __fadd_rn(cz, -base[p1 * 3 + 2]);
        const float sq1 = __fadd_rn(__fadd_rn(__fmul_rn(dx1, dx1), __fmul_rn(dy1, dy1)),
                                    __fmul_rn(dz1, dz1));
        const bool h0 = (sq0 <= R2);
        const bool h1 = (sq1 <= R2);
        const unsigned m0 = __ballot_sync(0xFFFFFFFFu, h0);
        const unsigned m1 = __ballot_sync(0xFFFFFFFFu, h1);
        if (h0) {
            const int pos = cnt + __popc(m0 & ((1u << lane) - 1u));
            if (pos < K_NB) s_idx[w][pos] = p0;
        }
        const int c1 = cnt + __popc(m0);
        if (h1) {
            const int pos = c1 + __popc(m1 & ((1u << lane) - 1u));
            if (pos < K_NB) s_idx[w][pos] = p1;
        }
        cnt = c1 + __popc(m1);
    }
    __syncwarp();
    const int first = s_idx[w][0];          // >=1 hit guaranteed (centroid itself)
    if (cnt < K_NB && lane >= cnt) s_idx[w][lane] = first;
    __syncwarp();

    // grouped_xyz (centered): one neighbor per lane
    {
        const int gi = s_idx[w][lane];
        float* go = out + GX_OFF + ((size_t)c * K_NB + lane) * 3;
        go[0] = __fadd_rn(base[gi * 3 + 0], -cx);
        go[1] = __fadd_rn(base[gi * 3 + 1], -cy);
        go[2] = __fadd_rn(base[gi * 3 + 2], -cz);
    }

    // grouped features: K neighbors x 128 floats, float4 per lane per row
    const float4* f4 = (const float4*)feat;
    float4* o4 = (float4*)(out + GF_OFF) + (size_t)c * K_NB * (C_FEAT / 4);
#pragma unroll 4
    for (int k = 0; k < K_NB; ++k) {
        const int gi = s_idx[w][k];
        o4[(size_t)k * (C_FEAT / 4) + lane] =
            f4[((size_t)b * N_PTS + gi) * (C_FEAT / 4) + lane];
    }
}

// ============================================================================
extern "C" void kernel_launch(void* const* d_in, const int* in_sizes, int n_in,
                              void* d_out, int out_size)
{
    const float* xyz  = (const float*)d_in[0];
    const float* feat = (const float*)d_in[1];
    if (n_in >= 2 && in_sizes[0] > in_sizes[1]) {   // defensive: xyz is smaller
        const float* tmp = xyz; xyz = feat; feat = tmp;
    }
    float* out = (float*)d_out;

    sort_kernel<<<B_SZ, N_CELLS>>>(xyz);
    fps_kernel<<<B_SZ, FPS_T>>>(xyz, out);
    group_kernel<<<(B_SZ * S_SAMPLES) / BQ_WARPS, BQ_WARPS * 32>>>(xyz, feat, out);
}

// round 4
// speedup vs baseline: 1.4062x; 1.4062x over previous
#include <cuda_runtime.h>
#include <cstdint>

#define N_PTS      16384
#define B_SZ       4
#define S_SAMPLES  1024
#define K_NB       32
#define C_FEAT     128

#define CEN_OFF    0
#define GX_OFF     (B_SZ * S_SAMPLES * 3)                      // 12288
#define GF_OFF     (GX_OFF + B_SZ * S_SAMPLES * K_NB * 3)     // 405504

#define FPS_T      512
#define PPT        32                   // points per thread (sorted, contiguous)
#define N_CELLS    512                  // 8x8x8 spatial grid

typedef unsigned long long ull;

// ---------------- packed f32x2 helpers (exact per-lane round-to-nearest) ----
__device__ __forceinline__ ull pack2(float lo, float hi) {
    ull r; asm("mov.b64 %0, {%1, %2};" : "=l"(r) : "f"(lo), "f"(hi)); return r;
}
__device__ __forceinline__ void unpack2(ull v, float& lo, float& hi) {
    asm("mov.b64 {%0, %1}, %2;" : "=f"(lo), "=f"(hi) : "l"(v));
}
__device__ __forceinline__ ull addx2(ull a, ull b) {
    ull r; asm("add.rn.f32x2 %0, %1, %2;" : "=l"(r) : "l"(a), "l"(b)); return r;
}
__device__ __forceinline__ ull mulx2(ull a, ull b) {
    ull r; asm("mul.rn.f32x2 %0, %1, %2;" : "=l"(r) : "l"(a), "l"(b)); return r;
}

// ---------------- spatially sorted scratch (device globals: no allocs) ------
__device__ float g_sx[B_SZ * N_PTS];
__device__ float g_sy[B_SZ * N_PTS];
__device__ float g_sz[B_SZ * N_PTS];
__device__ int   g_sid[B_SZ * N_PTS];

__device__ __forceinline__ int cell_of(float x, float y, float z) {
    int cx = min(max((int)(x * 8.0f), 0), 7);
    int cy = min(max((int)(y * 8.0f), 0), 7);
    int cz = min(max((int)(z * 8.0f), 0), 7);
    return (cx << 6) | (cy << 3) | cz;
}

// ============================================================================
// Counting sort by 8x8x8 cell. One CTA (1024 thr) per batch. In-cell order is
// nondeterministic (atomics) but FPS output is order-independent (order-free
// min updates + order-free 64-bit argmax keys with original-index tiebreak).
// ============================================================================
__global__ __launch_bounds__(1024)
void sort_kernel(const float* __restrict__ xyz)
{
    __shared__ int hist[N_CELLS];
    __shared__ int wsum[16];
    const int t = threadIdx.x;
    const int b = blockIdx.x;
    const float* base = xyz + (size_t)b * N_PTS * 3;

    if (t < N_CELLS) hist[t] = 0;
    __syncthreads();
    for (int i = t; i < N_PTS; i += 1024)
        atomicAdd(&hist[cell_of(base[3 * i], base[3 * i + 1], base[3 * i + 2])], 1);
    __syncthreads();

    int incl = 0, own = 0;
    const int lane = t & 31, w = t >> 5;
    if (t < N_CELLS) {
        own = hist[t];
        incl = own;
#pragma unroll
        for (int off = 1; off < 32; off <<= 1) {
            int n = __shfl_up_sync(0xFFFFFFFFu, incl, off);
            if (lane >= off) incl += n;
        }
        if (lane == 31) wsum[w] = incl;
    }
    __syncthreads();
    if (t < 32) {
        int v = (t < 16) ? wsum[t] : 0;
#pragma unroll
        for (int off = 1; off < 16; off <<= 1) {
            int n = __shfl_up_sync(0xFFFFFFFFu, v, off);
            if (t >= off) v += n;
        }
        if (t < 16) wsum[t] = v;        // inclusive warp sums
    }
    __syncthreads();
    if (t < N_CELLS) {
        hist[t] = incl - own + (w ? wsum[w - 1] : 0);   // exclusive offsets
    }
    __syncthreads();
    for (int i = t; i < N_PTS; i += 1024) {
        const float x = base[3 * i], y = base[3 * i + 1], z = base[3 * i + 2];
        const int pos = atomicAdd(&hist[cell_of(x, y, z)], 1);
        const int o = b * N_PTS + pos;
        g_sx[o] = x; g_sy[o] = y; g_sz[o] = z; g_sid[o] = i;
    }
}

// ============================================================================
// FPS with exact bounding-box pruning. One CTA per batch, 512 threads, each
// owning 32 spatially-contiguous sorted points. Coords in registers, min_d +
// sorted ids in SMEM (thread-minor float4 layout, conflict-free).
//   skip thread iff  rd(lb2_rd * 0.99999) >= thread_vmax
// (safe: 1e-5 margin dominates the <=4-ulp under-rounding of the rn chain).
// Argmax key = (float_bits(vmax)<<32) | (0xFFFFFFFF - orig_idx): max key ==
// (max value, first-occurrence original index) for any scan order.
// Reduction: warp shfl -> smem atomicMax(u64) on a 3-slot rotating cell ->
// ONE __syncthreads per iteration; winner coords via broadcast __ldg.
// ============================================================================
extern __shared__ unsigned char fps_smraw[];

__device__ __forceinline__ int lds_sid(const int* s_sid, int t, int j) {
    return s_sid[(((j >> 2) * FPS_T + t) << 2) + (j & 3)];
}

__global__ __launch_bounds__(FPS_T, 1)
void fps_kernel(const float* __restrict__ xyz, float* __restrict__ out)
{
    float4* s_m4  = (float4*)fps_smraw;                         // [8 * 512]
    int*    s_sid = (int*)(fps_smraw + 8 * FPS_T * 16);         // [16384]
    __shared__ ull s_red[3];

    const int t = threadIdx.x;
    const int b = blockIdx.x;
    const int lane = t & 31;
    const int gb = b * N_PTS + t * PPT;
    float* cen = out + CEN_OFF + (size_t)b * S_SAMPLES * 3;

    // coords in registers: pair p holds sorted points 32t+2p, 32t+2p+1
    ull X[PPT / 2], Y[PPT / 2], Z[PPT / 2];
    float blx = 1e30f, bly = 1e30f, blz = 1e30f;
    float bhx = -1e30f, bhy = -1e30f, bhz = -1e30f;
#pragma unroll
    for (int p = 0; p < PPT / 2; ++p) {
        const int i0 = gb + 2 * p, i1 = i0 + 1;
        const float x0 = g_sx[i0], x1 = g_sx[i1];
        const float y0 = g_sy[i0], y1 = g_sy[i1];
        const float z0 = g_sz[i0], z1 = g_sz[i1];
        X[p] = pack2(x0, x1); Y[p] = pack2(y0, y1); Z[p] = pack2(z0, z1);
        blx = fminf(blx, fminf(x0, x1)); bhx = fmaxf(bhx, fmaxf(x0, x1));
        bly = fminf(bly, fminf(y0, y1)); bhy = fmaxf(bhy, fmaxf(y0, y1));
        blz = fminf(blz, fminf(z0, z1)); bhz = fmaxf(bhz, fmaxf(z0, z1));
    }
#pragma unroll
    for (int q = 0; q < 8; ++q) {
        s_m4[q * FPS_T + t] = make_float4(1e10f, 1e10f, 1e10f, 1e10f);
#pragma unroll
        for (int r = 0; r < 4; ++r)
            s_sid[((q * FPS_T + t) << 2) + r] = g_sid[gb + 4 * q + r];
    }
    if (t < 3) s_red[t] = 0ull;

    const float* obase = xyz + (size_t)b * N_PTS * 3;
    float cx = __ldg(obase + 0), cy = __ldg(obase + 1), cz = __ldg(obase + 2);
    if (t == 0) { cen[0] = cx; cen[1] = cy; cen[2] = cz; }

    float vmax = 1e10f;        // forces full update on first iteration
    ull ckey = 0;
    __syncthreads();

    for (int s = 1; s < S_SAMPLES; ++s) {
        // conservative (round-down) lower bound on dist^2(centroid, thread BB)
        const float dx = fmaxf(fmaxf(__fsub_rd(blx, cx), __fsub_rd(cx, bhx)), 0.0f);
        const float dy = fmaxf(fmaxf(__fsub_rd(bly, cy), __fsub_rd(cy, bhy)), 0.0f);
        const float dz = fmaxf(fmaxf(__fsub_rd(blz, cz), __fsub_rd(cz, bhz)), 0.0f);
        const float lb2 = __fadd_rd(__fadd_rd(__fmul_rd(dx, dx), __fmul_rd(dy, dy)),
                                    __fmul_rd(dz, dz));
        const float lb2s = __fmul_rd(lb2, 0.99999f);

        if (lb2s < vmax) {
            const ull nx = pack2(-cx, -cx);
            const ull ny = pack2(-cy, -cy);
            const ull nz = pack2(-cz, -cz);
            float lmax = -1.0f;
            int bj = 0, bsid = -1;
#pragma unroll
            for (int q = 0; q < 8; ++q) {
                float4 m = s_m4[q * FPS_T + t];
                ull ddx = addx2(X[2 * q], nx);
                ull ddy = addx2(Y[2 * q], ny);
                ull ddz = addx2(Z[2 * q], nz);
                ull d2a = addx2(addx2(mulx2(ddx, ddx), mulx2(ddy, ddy)),
                                mulx2(ddz, ddz));
                ddx = addx2(X[2 * q + 1], nx);
                ddy = addx2(Y[2 * q + 1], ny);
                ddz = addx2(Z[2 * q + 1], nz);
                ull d2b = addx2(addx2(mulx2(ddx, ddx), mulx2(ddy, ddy)),
                                mulx2(ddz, ddz));
                float d0, d1, d2, d3;
                unpack2(d2a, d0, d1); unpack2(d2b, d2, d3);
                m.x = fminf(m.x, d0); m.y = fminf(m.y, d1);
                m.z = fminf(m.z, d2); m.w = fminf(m.w, d3);
                s_m4[q * FPS_T + t] = m;

                // track (max value, min original index on exact ties)
                const int j0 = 4 * q;
                if (m.x > lmax) { lmax = m.x; bj = j0;     bsid = -1; }
                else if (m.x == lmax) {
                    int s1 = (bsid < 0) ? lds_sid(s_sid, t, bj) : bsid;
                    bsid = min(s1, lds_sid(s_sid, t, j0));
                }
                if (m.y > lmax) { lmax = m.y; bj = j0 + 1; bsid = -1; }
                else if (m.y == lmax) {
                    int s1 = (bsid < 0) ? lds_sid(s_sid, t, bj) : bsid;
                    bsid = min(s1, lds_sid(s_sid, t, j0 + 1));
                }
                if (m.z > lmax) { lmax = m.z; bj = j0 + 2; bsid = -1; }
                else if (m.z == lmax) {
                    int s1 = (bsid < 0) ? lds_sid(s_sid, t, bj) : bsid;
                    bsid = min(s1, lds_sid(s_sid, t, j0 + 2));
                }
                if (m.w > lmax) { lmax = m.w; bj = j0 + 3; bsid = -1; }
                else if (m.w == lmax) {
                    int s1 = (bsid < 0) ? lds_sid(s_sid, t, bj) : bsid;
                    bsid = min(s1, lds_sid(s_sid, t, j0 + 3));
                }
            }
            if (bsid < 0) bsid = lds_sid(s_sid, t, bj);
            vmax = lmax;
            ckey = ((ull)__float_as_uint(lmax) << 32)
                 | (unsigned)(0xFFFFFFFFu - (unsigned)bsid);
        }

        // ---- CTA argmax: warp shfl reduce, then one smem atomicMax ----
        ull key = ckey;
#pragma unroll
        for (int off = 16; off > 0; off >>= 1) {
            ull o = __shfl_down_sync(0xFFFFFFFFu, key, off);
            if (o > key) key = o;
        }
        const int slot = s % 3;
        if (lane == 0) atomicMax(&s_red[slot], key);
        __syncthreads();
        const ull gk = s_red[slot];
        if (t == 0) s_red[(s + 2) % 3] = 0ull;   // reset slot used at iter s-1
                                                 // (safe: next written after sync(s+1))
        const int widx = (int)(0xFFFFFFFFu - (unsigned)gk);
        cx = __ldg(obase + widx * 3 + 0);        // broadcast, L1-resident
        cy = __ldg(obase + widx * 3 + 1);
        cz = __ldg(obase + widx * 3 + 2);
        if (t == 0) { cen[s * 3 + 0] = cx; cen[s * 3 + 1] = cy; cen[s * 3 + 2] = cz; }
    }
}

// ============================================================================
// Ball query + gather: one warp per centroid, 64 pts per ballot iteration,
// early exit at K hits. First 2048 points cached in SMEM per block (expected
// scan ~955 pts), gmem fallback for the tail. Scan order == ascending index.
// ============================================================================
#define BQ_WARPS   8
#define BQ_CACHE   2048

__global__ __launch_bounds__(BQ_WARPS * 32)
void group_kernel(const float* __restrict__ xyz,
                  const float* __restrict__ feat,
                  float* __restrict__ out)
{
    __shared__ float s_pts[BQ_CACHE * 3];
    __shared__ int   s_idx[BQ_WARPS][K_NB];

    const int tid  = threadIdx.x;
    const int w    = tid >> 5;
    const int lane = tid & 31;
    const int c    = blockIdx.x * BQ_WARPS + w;          // centroid id
    const int b    = c >> 10;                            // 128 blocks per batch
    const float* base = xyz + (size_t)b * N_PTS * 3;

    for (int i = tid; i < BQ_CACHE * 3; i += BQ_WARPS * 32) s_pts[i] = base[i];
    __syncthreads();

    const float* cen = out + CEN_OFF + (size_t)c * 3;
    const float cx = __ldg(cen + 0), cy = __ldg(cen + 1), cz = __ldg(cen + 2);
    const float R2 = (float)(0.2 * 0.2);

    int cnt = 0;
    // ---- smem prefix ----
    for (int j = 0; j < BQ_CACHE / 64 && cnt < K_NB; ++j) {
        const int p0 = j * 64 + lane;
        const int p1 = p0 + 32;
        const float dx0 = __fadd_rn(cx, -s_pts[p0 * 3 + 0]);
        const float dy0 = __fadd_rn(cy, -s_pts[p0 * 3 + 1]);
        const float dz0 = __fadd_rn(cz, -s_pts[p0 * 3 + 2]);
        const float sq0 = __fadd_rn(__fadd_rn(__fmul_rn(dx0, dx0), __fmul_rn(dy0, dy0)),
                                    __fmul_rn(dz0, dz0));
        const float dx1 = __fadd_rn(cx, -s_pts[p1 * 3 + 0]);
        const float dy1 = __fadd_rn(cy, -s_pts[p1 * 3 + 1]);
        const float dz1 = __fadd_rn(cz, -s_pts[p1 * 3 + 2]);
        const float sq1 = __fadd_rn(__fadd_rn(__fmul_rn(dx1, dx1), __fmul_rn(dy1, dy1)),
                                    __fmul_rn(dz1, dz1));
        const bool h0 = (sq0 <= R2);
        const bool h1 = (sq1 <= R2);
        const unsigned m0 = __ballot_sync(0xFFFFFFFFu, h0);
        const unsigned m1 = __ballot_sync(0xFFFFFFFFu, h1);
        if (h0) {
            const int pos = cnt + __popc(m0 & ((1u << lane) - 1u));
            if (pos < K_NB) s_idx[w][pos] = p0;
        }
        const int c1 = cnt + __popc(m0);
        if (h1) {
            const int pos = c1 + __popc(m1 & ((1u << lane) - 1u));
            if (pos < K_NB) s_idx[w][pos] = p1;
        }
        cnt = c1 + __popc(m1);
    }
    // ---- gmem tail (rare) ----
    for (int j = BQ_CACHE / 64; j < N_PTS / 64 && cnt < K_NB; ++j) {
        const int p0 = j * 64 + lane;
        const int p1 = p0 + 32;
        const float dx0 = __fadd_rn(cx, -base[p0 * 3 + 0]);
        const float dy0 = __fadd_rn(cy, -base[p0 * 3 + 1]);
        const float dz0 = __fadd_rn(cz, -base[p0 * 3 + 2]);
        const float sq0 = __fadd_rn(__fadd_rn(__fmul_rn(dx0, dx0), __fmul_rn(dy0, dy0)),
                                    __fmul_rn(dz0, dz0));
        const float dx1 = __fadd_rn(cx, -base[p1 * 3 + 0]);
        const float dy1 = __fadd_rn(cy, -base[p1 * 3 + 1]);
        const float dz1 = __fadd_rn(cz, -base[p1 * 3 + 2]);
        const float sq1 = __fadd_rn(__fadd_rn(__fmul_rn(dx1, dx1), __fmul_rn(dy1, dy1)),
                                    __fmul_rn(dz1, dz1));
        const bool h0 = (sq0 <= R2);
        const bool h1 = (sq1 <= R2);
        const unsigned m0 = __ballot_sync(0xFFFFFFFFu, h0);
        const unsigned m1 = __ballot_sync(0xFFFFFFFFu, h1);
        if (h0) {
            const int pos = cnt + __popc(m0 & ((1u << lane) - 1u));
            if (pos < K_NB) s_idx[w][pos] = p0;
        }
        const int c1 = cnt + __popc(m0);
        if (h1) {
            const int pos = c1 + __popc(m1 & ((1u << lane) - 1u));
            if (pos < K_NB) s_idx[w][pos] = p1;
        }
        cnt = c1 + __popc(m1);
    }
    __syncwarp();
    const int first = s_idx[w][0];          // >=1 hit guaranteed (centroid itself)
    if (cnt < K_NB && lane >= cnt) s_idx[w][lane] = first;
    __syncwarp();

    // grouped_xyz (centered): one neighbor per lane
    {
        const int gi = s_idx[w][lane];
        float* go = out + GX_OFF + ((size_t)c * K_NB + lane) * 3;
        go[0] = __fadd_rn(base[gi * 3 + 0], -cx);
        go[1] = __fadd_rn(base[gi * 3 + 1], -cy);
        go[2] = __fadd_rn(base[gi * 3 + 2], -cz);
    }

    // grouped features: K neighbors x 128 floats, float4 per lane per row
    const float4* f4 = (const float4*)feat;
    float4* o4 = (float4*)(out + GF_OFF) + (size_t)c * K_NB * (C_FEAT / 4);
#pragma unroll 4
    for (int k = 0; k < K_NB; ++k) {
        const int gi = s_idx[w][k];
        o4[(size_t)k * (C_FEAT / 4) + lane] =
            f4[((size_t)b * N_PTS + gi) * (C_FEAT / 4) + lane];
    }
}

// ============================================================================
extern "C" void kernel_launch(void* const* d_in, const int* in_sizes, int n_in,
                              void* d_out, int out_size)
{
    const float* xyz  = (const float*)d_in[0];
    const float* feat = (const float*)d_in[1];
    if (n_in >= 2 && in_sizes[0] > in_sizes[1]) {   // defensive: xyz is smaller
        const float* tmp = xyz; xyz = feat; feat = tmp;
    }
    float* out = (float*)d_out;

    const int fps_smem = 8 * FPS_T * 16 + N_PTS * 4;   // min_d (f4) + sorted ids
    cudaFuncSetAttribute(fps_kernel, cudaFuncAttributeMaxDynamicSharedMemorySize,
                         fps_smem);

    sort_kernel<<<B_SZ, 1024>>>(xyz);
    fps_kernel<<<B_SZ, FPS_T, fps_smem>>>(xyz, out);
    group_kernel<<<(B_SZ * S_SAMPLES) / BQ_WARPS, BQ_WARPS * 32>>>(xyz, feat, out);
}

// round 6
// speedup vs baseline: 1.7360x; 1.2345x over previous
#include <cuda_runtime.h>
#include <cstdint>

#define N_PTS      16384
#define B_SZ       4
#define S_SAMPLES  1024
#define K_NB       32
#define C_FEAT     128

#define CEN_OFF    0
#define GX_OFF     (B_SZ * S_SAMPLES * 3)                      // 12288
#define GF_OFF     (GX_OFF + B_SZ * S_SAMPLES * K_NB * 3)     // 405504

#define FPS_T      512
#define N_GRP      512                  // groups of 32 sorted points
#define N_CELLS    512                  // 8x8x8 spatial grid

typedef unsigned long long ull;

// Initial group key: value = 1e10f (reference's init), index payload = 0.
// MUST be a finite float in the hi bits -- NaN there disables all pruning
// comparisons and breaks the whole iteration (R5 bug).
#define KEY_INIT   ((ull)0x501502F9u << 32)    // __float_as_uint(1e10f) << 32

// ---------------- spatially sorted points (device globals: no allocs) -------
// float4 = (x, y, z, bitcast original index)
__device__ float4 g_pts[B_SZ * N_PTS];

__device__ __forceinline__ int cell_of(float x, float y, float z) {
    int cx = min(max((int)(x * 8.0f), 0), 7);
    int cy = min(max((int)(y * 8.0f), 0), 7);
    int cz = min(max((int)(z * 8.0f), 0), 7);
    return (cx << 6) | (cy << 3) | cz;
}

// ============================================================================
// Counting sort by 8x8x8 cell. One CTA (1024 thr) per batch. In-cell order is
// nondeterministic (atomics) but FPS output is order-independent (order-free
// min updates + order-free 64-bit argmax keys with original-index tiebreak).
// ============================================================================
__global__ __launch_bounds__(1024)
void sort_kernel(const float* __restrict__ xyz)
{
    __shared__ int hist[N_CELLS];
    __shared__ int wsum[16];
    const int t = threadIdx.x;
    const int b = blockIdx.x;
    const float* base = xyz + (size_t)b * N_PTS * 3;

    if (t < N_CELLS) hist[t] = 0;
    __syncthreads();
    for (int i = t; i < N_PTS; i += 1024)
        atomicAdd(&hist[cell_of(base[3 * i], base[3 * i + 1], base[3 * i + 2])], 1);
    __syncthreads();

    int incl = 0, own = 0;
    const int lane = t & 31, w = t >> 5;
    if (t < N_CELLS) {
        own = hist[t];
        incl = own;
#pragma unroll
        for (int off = 1; off < 32; off <<= 1) {
            int n = __shfl_up_sync(0xFFFFFFFFu, incl, off);
            if (lane >= off) incl += n;
        }
        if (lane == 31) wsum[w] = incl;
    }
    __syncthreads();
    if (t < 32) {
        int v = (t < 16) ? wsum[t] : 0;
#pragma unroll
        for (int off = 1; off < 16; off <<= 1) {
            int n = __shfl_up_sync(0xFFFFFFFFu, v, off);
            if (t >= off) v += n;
        }
        if (t < 16) wsum[t] = v;        // inclusive warp sums
    }
    __syncthreads();
    if (t < N_CELLS) hist[t] = incl - own + (w ? wsum[w - 1] : 0);  // exclusive
    __syncthreads();
    for (int i = t; i < N_PTS; i += 1024) {
        const float x = base[3 * i], y = base[3 * i + 1], z = base[3 * i + 2];
        const int pos = atomicAdd(&hist[cell_of(x, y, z)], 1);
        g_pts[b * N_PTS + pos] = make_float4(x, y, z, __int_as_float(i));
    }
}

// ============================================================================
// Task-parallel pruned FPS. One CTA (512 thr) per batch.
// Group g = 32 contiguous sorted points. Thread g owns group g's BB (regs).
// Per iteration:
//  P1: thread g tests  rd(lb2_rd(c, BB_g) * 0.99999) < ub_g  (ub_g = hi bits
//      of group key = current max min_d in g); active groups compacted into a
//      worklist (ballot + atomicAdd). Skip is provably exact (1e-5 margin >>
//      4-ulp rn under-rounding; skipped updates cannot change any min_d).
//  P2: one WARP per active group, one point per lane: LDG.128 the float4,
//      min-update SMEM min_d, 5-shfl max-reduce of key=(bits(v)<<32)|~origidx,
//      rewrite group key. Pruned groups cost nothing.
//  P3: CTA argmax over 512 group keys (shfl + rotating-slot smem atomicMax).
// Winner coords via broadcast __ldg of original xyz.
// ============================================================================
extern __shared__ float fps_md[];        // min_d[16384]

__global__ __launch_bounds__(FPS_T, 1)
void fps_kernel(const float* __restrict__ xyz, float* __restrict__ out)
{
    __shared__ ull s_key[N_GRP];
    __shared__ int s_act[N_GRP];
    __shared__ int s_cnt[2];
    __shared__ ull s_red[3];

    const int t = threadIdx.x;
    const int b = blockIdx.x;
    const int lane = t & 31, w = t >> 5;
    float* cen = out + CEN_OFF + (size_t)b * S_SAMPLES * 3;
    const float* obase = xyz + (size_t)b * N_PTS * 3;
    const float4* pbase = g_pts + b * N_PTS;

    // ---- setup: group BB in registers of thread t, init min_d / keys ----
    float blx = 1e30f, bly = 1e30f, blz = 1e30f;
    float bhx = -1e30f, bhy = -1e30f, bhz = -1e30f;
#pragma unroll 4
    for (int j = 0; j < 32; ++j) {
        const float4 p = __ldg(&pbase[t * 32 + j]);
        blx = fminf(blx, p.x); bhx = fmaxf(bhx, p.x);
        bly = fminf(bly, p.y); bhy = fmaxf(bhy, p.y);
        blz = fminf(blz, p.z); bhz = fmaxf(bhz, p.z);
        fps_md[t * 32 + j] = 1e10f;
    }
    s_key[t] = KEY_INIT;                 // finite ub=1e10 -> all active iter 1
    if (t < 2) s_cnt[t] = 0;
    if (t < 3) s_red[t] = 0ull;

    float cx = __ldg(obase + 0), cy = __ldg(obase + 1), cz = __ldg(obase + 2);
    if (t == 0) { cen[0] = cx; cen[1] = cy; cen[2] = cz; }
    __syncthreads();

    for (int s = 1; s < S_SAMPLES; ++s) {
        const int par = s & 1;

        // ---- P1: prune + compact ----
        const float dx = fmaxf(fmaxf(__fsub_rd(blx, cx), __fsub_rd(cx, bhx)), 0.0f);
        const float dy = fmaxf(fmaxf(__fsub_rd(bly, cy), __fsub_rd(cy, bhy)), 0.0f);
        const float dz = fmaxf(fmaxf(__fsub_rd(blz, cz), __fsub_rd(cz, bhz)), 0.0f);
        const float lb2 = __fadd_rd(__fadd_rd(__fmul_rd(dx, dx), __fmul_rd(dy, dy)),
                                    __fmul_rd(dz, dz));
        const float ub  = __uint_as_float((unsigned)(s_key[t] >> 32));
        const bool active = (__fmul_rd(lb2, 0.99999f) < ub);

        const unsigned mask = __ballot_sync(0xFFFFFFFFu, active);
        int base = 0;
        if (lane == 0) base = atomicAdd(&s_cnt[par], __popc(mask));
        base = __shfl_sync(0xFFFFFFFFu, base, 0);
        if (active)
            s_act[base + __popc(mask & ((1u << lane) - 1u))] = t;
        __syncthreads();                               // sync1
        const int A = s_cnt[par];
        if (t == 0) s_cnt[par ^ 1] = 0;   // last read at iter s-1; next write s+1

        // ---- P2: warp per active group ----
        for (int task = w; task < A; task += FPS_T / 32) {
            const int g = s_act[task];
            const float4 p = __ldg(&pbase[g * 32 + lane]);
            const float ddx = __fadd_rn(p.x, -cx);
            const float ddy = __fadd_rn(p.y, -cy);
            const float ddz = __fadd_rn(p.z, -cz);
            const float d2 = __fadd_rn(__fadd_rn(__fmul_rn(ddx, ddx),
                                                 __fmul_rn(ddy, ddy)),
                                       __fmul_rn(ddz, ddz));
            const float nm = fminf(fps_md[g * 32 + lane], d2);
            fps_md[g * 32 + lane] = nm;
            ull key = ((ull)__float_as_uint(nm) << 32)
                    | (unsigned)(0xFFFFFFFFu - (unsigned)__float_as_int(p.w));
#pragma unroll
            for (int off = 16; off > 0; off >>= 1) {
                ull o = __shfl_down_sync(0xFFFFFFFFu, key, off);
                if (o > key) key = o;
            }
            if (lane == 0) s_key[g] = key;
        }
        __syncthreads();                               // sync2

        // ---- P3: CTA argmax over 512 group keys ----
        ull key = s_key[t];
#pragma unroll
        for (int off = 16; off > 0; off >>= 1) {
            ull o = __shfl_down_sync(0xFFFFFFFFu, key, off);
            if (o > key) key = o;
        }
        const int slot = s % 3;
        if (lane == 0) atomicMax(&s_red[slot], key);
        __syncthreads();                               // sync3
        const ull gk = s_red[slot];
        if (t == 0) s_red[(s + 2) % 3] = 0ull;         // slot of iter s-1

        const int widx = (int)(0xFFFFFFFFu - (unsigned)gk);
        cx = __ldg(obase + widx * 3 + 0);              // broadcast
        cy = __ldg(obase + widx * 3 + 1);
        cz = __ldg(obase + widx * 3 + 2);
        if (t == 0) { cen[s * 3 + 0] = cx; cen[s * 3 + 1] = cy; cen[s * 3 + 2] = cz; }
    }
}

// ============================================================================
// Ball query + gather: one warp per centroid, 64 pts per ballot iteration,
// early exit at K hits. First 2048 points cached in SMEM per block; gmem tail.
// Scan order == ascending index == reference top_k order.
// ============================================================================
#define BQ_WARPS   8
#define BQ_CACHE   2048

__global__ __launch_bounds__(BQ_WARPS * 32)
void group_kernel(const float* __restrict__ xyz,
                  const float* __restrict__ feat,
                  float* __restrict__ out)
{
    __shared__ float s_pts[BQ_CACHE * 3];
    __shared__ int   s_idx[BQ_WARPS][K_NB];

    const int tid  = threadIdx.x;
    const int w    = tid >> 5;
    const int lane = tid & 31;
    const int c    = blockIdx.x * BQ_WARPS + w;          // centroid id
    const int b    = c >> 10;                            // 128 blocks per batch
    const float* base = xyz + (size_t)b * N_PTS * 3;

    for (int i = tid; i < BQ_CACHE * 3; i += BQ_WARPS * 32) s_pts[i] = base[i];
    __syncthreads();

    const float* cen = out + CEN_OFF + (size_t)c * 3;
    const float cx = __ldg(cen + 0), cy = __ldg(cen + 1), cz = __ldg(cen + 2);
    const float R2 = (float)(0.2 * 0.2);

    int cnt = 0;
    for (int j = 0; j < BQ_CACHE / 64 && cnt < K_NB; ++j) {
        const int p0 = j * 64 + lane;
        const int p1 = p0 + 32;
        const float dx0 = __fadd_rn(cx, -s_pts[p0 * 3 + 0]);
        const float dy0 = __fadd_rn(cy, -s_pts[p0 * 3 + 1]);
        const float dz0 = __fadd_rn(cz, -s_pts[p0 * 3 + 2]);
        const float sq0 = __fadd_rn(__fadd_rn(__fmul_rn(dx0, dx0), __fmul_rn(dy0, dy0)),
                                    __fmul_rn(dz0, dz0));
        const float dx1 = __fadd_rn(cx, -s_pts[p1 * 3 + 0]);
        const float dy1 = __fadd_rn(cy, -s_pts[p1 * 3 + 1]);
        const float dz1 = __fadd_rn(cz, -s_pts[p1 * 3 + 2]);
        const float sq1 = __fadd_rn(__fadd_rn(__fmul_rn(dx1, dx1), __fmul_rn(dy1, dy1)),
                                    __fmul_rn(dz1, dz1));
        const bool h0 = (sq0 <= R2);
        const bool h1 = (sq1 <= R2);
        const unsigned m0 = __ballot_sync(0xFFFFFFFFu, h0);
        const unsigned m1 = __ballot_sync(0xFFFFFFFFu, h1);
        if (h0) {
            const int pos = cnt + __popc(m0 & ((1u << lane) - 1u));
            if (pos < K_NB) s_idx[w][pos] = p0;
        }
        const int c1 = cnt + __popc(m0);
        if (h1) {
            const int pos = c1 + __popc(m1 & ((1u << lane) - 1u));
            if (pos < K_NB) s_idx[w][pos] = p1;
        }
        cnt = c1 + __popc(m1);
    }
    for (int j = BQ_CACHE / 64; j < N_PTS / 64 && cnt < K_NB; ++j) {
        const int p0 = j * 64 + lane;
        const int p1 = p0 + 32;
        const float dx0 = __fadd_rn(cx, -base[p0 * 3 + 0]);
        const float dy0 = __fadd_rn(cy, -base[p0 * 3 + 1]);
        const float dz0 = __fadd_rn(cz, -base[p0 * 3 + 2]);
        const float sq0 = __fadd_rn(__fadd_rn(__fmul_rn(dx0, dx0), __fmul_rn(dy0, dy0)),
                                    __fmul_rn(dz0, dz0));
        const float dx1 = __fadd_rn(cx, -base[p1 * 3 + 0]);
        const float dy1 = __fadd_rn(cy, -base[p1 * 3 + 1]);
        const float dz1 = __fadd_rn(cz, -base[p1 * 3 + 2]);
        const float sq1 = __fadd_rn(__fadd_rn(__fmul_rn(dx1, dx1), __fmul_rn(dy1, dy1)),
                                    __fmul_rn(dz1, dz1));
        const bool h0 = (sq0 <= R2);
        const bool h1 = (sq1 <= R2);
        const unsigned m0 = __ballot_sync(0xFFFFFFFFu, h0);
        const unsigned m1 = __ballot_sync(0xFFFFFFFFu, h1);
        if (h0) {
            const int pos = cnt + __popc(m0 & ((1u << lane) - 1u));
            if (pos < K_NB) s_idx[w][pos] = p0;
        }
        const int c1 = cnt + __popc(m0);
        if (h1) {
            const int pos = c1 + __popc(m1 & ((1u << lane) - 1u));
            if (pos < K_NB) s_idx[w][pos] = p1;
        }
        cnt = c1 + __popc(m1);
    }
    __syncwarp();
    const int first = s_idx[w][0];          // >=1 hit guaranteed (centroid itself)
    if (cnt < K_NB && lane >= cnt) s_idx[w][lane] = first;
    __syncwarp();

    {
        const int gi = s_idx[w][lane];
        float* go = out + GX_OFF + ((size_t)c * K_NB + lane) * 3;
        go[0] = __fadd_rn(base[gi * 3 + 0], -cx);
        go[1] = __fadd_rn(base[gi * 3 + 1], -cy);
        go[2] = __fadd_rn(base[gi * 3 + 2], -cz);
    }

    const float4* f4 = (const float4*)feat;
    float4* o4 = (float4*)(out + GF_OFF) + (size_t)c * K_NB * (C_FEAT / 4);
#pragma unroll 4
    for (int k = 0; k < K_NB; ++k) {
        const int gi = s_idx[w][k];
        o4[(size_t)k * (C_FEAT / 4) + lane] =
            f4[((size_t)b * N_PTS + gi) * (C_FEAT / 4) + lane];
    }
}

// ============================================================================
extern "C" void kernel_launch(void* const* d_in, const int* in_sizes, int n_in,
                              void* d_out, int out_size)
{
    const float* xyz  = (const float*)d_in[0];
    const float* feat = (const float*)d_in[1];
    if (n_in >= 2 && in_sizes[0] > in_sizes[1]) {   // defensive: xyz is smaller
        const float* tmp = xyz; xyz = feat; feat = tmp;
    }
    float* out = (float*)d_out;

    const int fps_smem = N_PTS * 4;     // min_d
    cudaFuncSetAttribute(fps_kernel, cudaFuncAttributeMaxDynamicSharedMemorySize,
                         fps_smem);

    sort_kernel<<<B_SZ, 1024>>>(xyz);
    fps_kernel<<<B_SZ, FPS_T, fps_smem>>>(xyz, out);
    group_kernel<<<(B_SZ * S_SAMPLES) / BQ_WARPS, BQ_WARPS * 32>>>(xyz, feat, out);
}

// round 7
// speedup vs baseline: 2.3406x; 1.3482x over previous
#include <cuda_runtime.h>
#include <cstdint>

#define N_PTS      16384
#define B_SZ       4
#define S_SAMPLES  1024
#define K_NB       32
#define C_FEAT     128

#define CEN_OFF    0
#define GX_OFF     (B_SZ * S_SAMPLES * 3)                      // 12288
#define GF_OFF     (GX_OFF + B_SZ * S_SAMPLES * K_NB * 3)     // 405504

#define FPS_T      1024                 // 32 warps
#define N_GRP      512                  // groups of 32 sorted points
#define N_CELLS    512                  // 8x8x8 spatial grid

typedef unsigned long long ull;

// Initial group key: value = 1e10f (reference init), index payload = 0.
// Hi bits MUST be a finite float (NaN kills the prune compare — R5 bug).
#define KEY_INIT   ((ull)0x501502F9u << 32)    // __float_as_uint(1e10f) << 32

// ---------------- spatially sorted points (device globals: no allocs) -------
// float4 = (x, y, z, bitcast original index)
__device__ float4 g_pts[B_SZ * N_PTS];

__device__ __forceinline__ int cell_of(float x, float y, float z) {
    int cx = min(max((int)(x * 8.0f), 0), 7);
    int cy = min(max((int)(y * 8.0f), 0), 7);
    int cz = min(max((int)(z * 8.0f), 0), 7);
    return (cx << 6) | (cy << 3) | cz;
}

// ============================================================================
// Counting sort by 8x8x8 cell. One CTA (1024 thr) per batch. In-cell order is
// nondeterministic (atomics) but FPS output is order-independent (order-free
// min updates + order-free (value, first-original-index) argmax).
// ============================================================================
__global__ __launch_bounds__(1024)
void sort_kernel(const float* __restrict__ xyz)
{
    __shared__ int hist[N_CELLS];
    __shared__ int wsum[16];
    const int t = threadIdx.x;
    const int b = blockIdx.x;
    const float* base = xyz + (size_t)b * N_PTS * 3;

    if (t < N_CELLS) hist[t] = 0;
    __syncthreads();
    for (int i = t; i < N_PTS; i += 1024)
        atomicAdd(&hist[cell_of(base[3 * i], base[3 * i + 1], base[3 * i + 2])], 1);
    __syncthreads();

    int incl = 0, own = 0;
    const int lane = t & 31, w = t >> 5;
    if (t < N_CELLS) {
        own = hist[t];
        incl = own;
#pragma unroll
        for (int off = 1; off < 32; off <<= 1) {
            int n = __shfl_up_sync(0xFFFFFFFFu, incl, off);
            if (lane >= off) incl += n;
        }
        if (lane == 31) wsum[w] = incl;
    }
    __syncthreads();
    if (t < 32) {
        int v = (t < 16) ? wsum[t] : 0;
#pragma unroll
        for (int off = 1; off < 16; off <<= 1) {
            int n = __shfl_up_sync(0xFFFFFFFFu, v, off);
            if (t >= off) v += n;
        }
        if (t < 16) wsum[t] = v;        // inclusive warp sums
    }
    __syncthreads();
    if (t < N_CELLS) hist[t] = incl - own + (w ? wsum[w - 1] : 0);  // exclusive
    __syncthreads();
    for (int i = t; i < N_PTS; i += 1024) {
        const float x = base[3 * i], y = base[3 * i + 1], z = base[3 * i + 2];
        const int pos = atomicAdd(&hist[cell_of(x, y, z)], 1);
        g_pts[b * N_PTS + pos] = make_float4(x, y, z, __int_as_float(i));
    }
}

// ============================================================================
// Task-parallel pruned FPS, atomic-free. One CTA (1024 thr = 32 warps)/batch.
// Group g (< 512) = 32 contiguous sorted points; thread g owns group BB (regs).
//  P1: prune  rd(lb2_rd * 0.99999) < ub_g  (ub = hi bits of group key); active
//      groups compacted via ballot + redundant 32-wide warp-count scan.
//  P2: one warp per active task, one point per lane, next-task prefetch;
//      group key rebuilt with 2x __reduce_max_sync (value, then ~idx on ties).
//  P3: CTA argmax: warp partials + redundant 32-entry reduce in every warp.
// Exactness: identical rn distance chain; skips only provably non-improving
// updates (1e-5 margin >> 4-ulp rn under-rounding); (max, first-orig-index)
// selection is scan-order-free. 4 __syncthreads/iter, zero atomics.
// ============================================================================
extern __shared__ float fps_md[];        // min_d[16384]

__global__ __launch_bounds__(FPS_T, 1)
void fps_kernel(const float* __restrict__ xyz, float* __restrict__ out)
{
    __shared__ ull s_key[N_GRP];
    __shared__ ull s_wkey[32];
    __shared__ int s_act[N_GRP];
    __shared__ int s_wcnt[32];

    const int t = threadIdx.x;
    const int b = blockIdx.x;
    const int lane = t & 31, w = t >> 5;
    float* cen = out + CEN_OFF + (size_t)b * S_SAMPLES * 3;
    const float* obase = xyz + (size_t)b * N_PTS * 3;
    const float4* pbase = g_pts + b * N_PTS;

    // ---- setup ----
    float blx = 1e30f, bly = 1e30f, blz = 1e30f;
    float bhx = -1e30f, bhy = -1e30f, bhz = -1e30f;
    if (t < N_GRP) {
#pragma unroll 4
        for (int j = 0; j < 32; ++j) {
            const float4 p = __ldg(&pbase[t * 32 + j]);
            blx = fminf(blx, p.x); bhx = fmaxf(bhx, p.x);
            bly = fminf(bly, p.y); bhy = fmaxf(bhy, p.y);
            blz = fminf(blz, p.z); bhz = fmaxf(bhz, p.z);
        }
        s_key[t] = KEY_INIT;
    }
#pragma unroll
    for (int j = 0; j < N_PTS / FPS_T; ++j)
        fps_md[j * FPS_T + t] = 1e10f;

    float cx = __ldg(obase + 0), cy = __ldg(obase + 1), cz = __ldg(obase + 2);
    if (t == 0) { cen[0] = cx; cen[1] = cy; cen[2] = cz; }
    __syncthreads();

    for (int s = 1; s < S_SAMPLES; ++s) {
        // ---- P1: prune + ballot ----
        bool active = false;
        if (t < N_GRP) {
            const float dx = fmaxf(fmaxf(__fsub_rd(blx, cx), __fsub_rd(cx, bhx)), 0.0f);
            const float dy = fmaxf(fmaxf(__fsub_rd(bly, cy), __fsub_rd(cy, bhy)), 0.0f);
            const float dz = fmaxf(fmaxf(__fsub_rd(blz, cz), __fsub_rd(cz, bhz)), 0.0f);
            const float lb2 = __fadd_rd(__fadd_rd(__fmul_rd(dx, dx), __fmul_rd(dy, dy)),
                                        __fmul_rd(dz, dz));
            const float ub = __uint_as_float((unsigned)(s_key[t] >> 32));
            active = (__fmul_rd(lb2, 0.99999f) < ub);
        }
        const unsigned mask = __ballot_sync(0xFFFFFFFFu, active);
        if (lane == 0) s_wcnt[w] = __popc(mask);
        __syncthreads();                                   // (1)

        // redundant per-warp scan of the 32 warp counts -> compaction offsets
        int v = s_wcnt[lane];
#pragma unroll
        for (int off = 1; off < 32; off <<= 1) {
            int n = __shfl_up_sync(0xFFFFFFFFu, v, off);
            if (lane >= off) v += n;
        }
        const int A = __shfl_sync(0xFFFFFFFFu, v, 31);
        const int wbase = (w == 0) ? 0 : __shfl_sync(0xFFFFFFFFu, v, w - 1);
        if (active)
            s_act[wbase + __popc(mask & ((1u << lane) - 1u))] = t;
        __syncthreads();                                   // (2)

        // ---- P2: warp per active task, next-task prefetch ----
        int task = w;
        int g = 0; float4 p = make_float4(0.f, 0.f, 0.f, 0.f);
        if (task < A) { g = s_act[task]; p = __ldg(&pbase[g * 32 + lane]); }
        while (task < A) {
            const int ntask = task + 32;
            int ng = 0; float4 np = p;
            if (ntask < A) { ng = s_act[ntask]; np = __ldg(&pbase[ng * 32 + lane]); }

            const float ddx = __fadd_rn(p.x, -cx);
            const float ddy = __fadd_rn(p.y, -cy);
            const float ddz = __fadd_rn(p.z, -cz);
            const float d2 = __fadd_rn(__fadd_rn(__fmul_rn(ddx, ddx),
                                                 __fmul_rn(ddy, ddy)),
                                       __fmul_rn(ddz, ddz));
            const float nm = fminf(fps_md[g * 32 + lane], d2);
            fps_md[g * 32 + lane] = nm;
            const unsigned vb = __float_as_uint(nm);         // min_d>=0: monotone bits
            const unsigned vmax = __reduce_max_sync(0xFFFFFFFFu, vb);
            const unsigned cand = (vb == vmax)
                ? (0xFFFFFFFFu - (unsigned)__float_as_int(p.w)) : 0u;
            const unsigned im = __reduce_max_sync(0xFFFFFFFFu, cand);
            if (lane == 0) s_key[g] = ((ull)vmax << 32) | im;

            task = ntask; g = ng; p = np;
        }
        __syncthreads();                                   // (3)

        // ---- P3: CTA argmax over 512 group keys ----
        const ull key = (t < N_GRP) ? s_key[t] : 0ull;
        const unsigned hi = (unsigned)(key >> 32), lo = (unsigned)key;
        const unsigned wv = __reduce_max_sync(0xFFFFFFFFu, hi);
        const unsigned wl = __reduce_max_sync(0xFFFFFFFFu, (hi == wv) ? lo : 0u);
        if (lane == 0) s_wkey[w] = ((ull)wv << 32) | wl;
        __syncthreads();                                   // (4)

        const ull k2 = s_wkey[lane];                        // 32 partials
        const unsigned h2 = (unsigned)(k2 >> 32), l2 = (unsigned)k2;
        const unsigned gv = __reduce_max_sync(0xFFFFFFFFu, h2);
        const unsigned gl = __reduce_max_sync(0xFFFFFFFFu, (h2 == gv) ? l2 : 0u);

        const int widx = (int)(0xFFFFFFFFu - gl);
        cx = __ldg(obase + widx * 3 + 0);                   // broadcast, L1-hot
        cy = __ldg(obase + widx * 3 + 1);
        cz = __ldg(obase + widx * 3 + 2);
        if (t == 0) { cen[s * 3 + 0] = cx; cen[s * 3 + 1] = cy; cen[s * 3 + 2] = cz; }
    }
}

// ============================================================================
// Ball query + gather: one warp per centroid, 64 pts per ballot iteration,
// early exit at K hits. First 2048 points cached in SMEM per block; gmem tail.
// Scan order == ascending index == reference top_k order.
// ============================================================================
#define BQ_WARPS   8
#define BQ_CACHE   2048

__global__ __launch_bounds__(BQ_WARPS * 32)
void group_kernel(const float* __restrict__ xyz,
                  const float* __restrict__ feat,
                  float* __restrict__ out)
{
    __shared__ float s_pts[BQ_CACHE * 3];
    __shared__ int   s_idx[BQ_WARPS][K_NB];

    const int tid  = threadIdx.x;
    const int w    = tid >> 5;
    const int lane = tid & 31;
    const int c    = blockIdx.x * BQ_WARPS + w;          // centroid id
    const int b    = c >> 10;                            // 128 blocks per batch
    const float* base = xyz + (size_t)b * N_PTS * 3;

    for (int i = tid; i < BQ_CACHE * 3; i += BQ_WARPS * 32) s_pts[i] = base[i];
    __syncthreads();

    const float* cen = out + CEN_OFF + (size_t)c * 3;
    const float cx = __ldg(cen + 0), cy = __ldg(cen + 1), cz = __ldg(cen + 2);
    const float R2 = (float)(0.2 * 0.2);

    int cnt = 0;
    for (int j = 0; j < BQ_CACHE / 64 && cnt < K_NB; ++j) {
        const int p0 = j * 64 + lane;
        const int p1 = p0 + 32;
        const float dx0 = __fadd_rn(cx, -s_pts[p0 * 3 + 0]);
        const float dy0 = __fadd_rn(cy, -s_pts[p0 * 3 + 1]);
        const float dz0 = __fadd_rn(cz, -s_pts[p0 * 3 + 2]);
        const float sq0 = __fadd_rn(__fadd_rn(__fmul_rn(dx0, dx0), __fmul_rn(dy0, dy0)),
                                    __fmul_rn(dz0, dz0));
        const float dx1 = __fadd_rn(cx, -s_pts[p1 * 3 + 0]);
        const float dy1 = __fadd_rn(cy, -s_pts[p1 * 3 + 1]);
        const float dz1 = __fadd_rn(cz, -s_pts[p1 * 3 + 2]);
        const float sq1 = __fadd_rn(__fadd_rn(__fmul_rn(dx1, dx1), __fmul_rn(dy1, dy1)),
                                    __fmul_rn(dz1, dz1));
        const bool h0 = (sq0 <= R2);
        const bool h1 = (sq1 <= R2);
        const unsigned m0 = __ballot_sync(0xFFFFFFFFu, h0);
        const unsigned m1 = __ballot_sync(0xFFFFFFFFu, h1);
        if (h0) {
            const int pos = cnt + __popc(m0 & ((1u << lane) - 1u));
            if (pos < K_NB) s_idx[w][pos] = p0;
        }
        const int c1 = cnt + __popc(m0);
        if (h1) {
            const int pos = c1 + __popc(m1 & ((1u << lane) - 1u));
            if (pos < K_NB) s_idx[w][pos] = p1;
        }
        cnt = c1 + __popc(m1);
    }
    for (int j = BQ_CACHE / 64; j < N_PTS / 64 && cnt < K_NB; ++j) {
        const int p0 = j * 64 + lane;
        const int p1 = p0 + 32;
        const float dx0 = __fadd_rn(cx, -base[p0 * 3 + 0]);
        const float dy0 = __fadd_rn(cy, -base[p0 * 3 + 1]);
        const float dz0 = __fadd_rn(cz, -base[p0 * 3 + 2]);
        const float sq0 = __fadd_rn(__fadd_rn(__fmul_rn(dx0, dx0), __fmul_rn(dy0, dy0)),
                                    __fmul_rn(dz0, dz0));
        const float dx1 = __fadd_rn(cx, -base[p1 * 3 + 0]);
        const float dy1 = __fadd_rn(cy, -base[p1 * 3 + 1]);
        const float dz1 = __fadd_rn(cz, -base[p1 * 3 + 2]);
        const float sq1 = __fadd_rn(__fadd_rn(__fmul_rn(dx1, dx1), __fmul_rn(dy1, dy1)),
                                    __fmul_rn(dz1, dz1));
        const bool h0 = (sq0 <= R2);
        const bool h1 = (sq1 <= R2);
        const unsigned m0 = __ballot_sync(0xFFFFFFFFu, h0);
        const unsigned m1 = __ballot_sync(0xFFFFFFFFu, h1);
        if (h0) {
            const int pos = cnt + __popc(m0 & ((1u << lane) - 1u));
            if (pos < K_NB) s_idx[w][pos] = p0;
        }
        const int c1 = cnt + __popc(m0);
        if (h1) {
            const int pos = c1 + __popc(m1 & ((1u << lane) - 1u));
            if (pos < K_NB) s_idx[w][pos] = p1;
        }
        cnt = c1 + __popc(m1);
    }
    __syncwarp();
    const int first = s_idx[w][0];          // >=1 hit guaranteed (centroid itself)
    if (cnt < K_NB && lane >= cnt) s_idx[w][lane] = first;
    __syncwarp();

    {
        const int gi = s_idx[w][lane];
        float* go = out + GX_OFF + ((size_t)c * K_NB + lane) * 3;
        go[0] = __fadd_rn(base[gi * 3 + 0], -cx);
        go[1] = __fadd_rn(base[gi * 3 + 1], -cy);
        go[2] = __fadd_rn(base[gi * 3 + 2], -cz);
    }

    const float4* f4 = (const float4*)feat;
    float4* o4 = (float4*)(out + GF_OFF) + (size_t)c * K_NB * (C_FEAT / 4);
#pragma unroll 4
    for (int k = 0; k < K_NB; ++k) {
        const int gi = s_idx[w][k];
        o4[(size_t)k * (C_FEAT / 4) + lane] =
            f4[((size_t)b * N_PTS + gi) * (C_FEAT / 4) + lane];
    }
}

// ============================================================================
extern "C" void kernel_launch(void* const* d_in, const int* in_sizes, int n_in,
                              void* d_out, int out_size)
{
    const float* xyz  = (const float*)d_in[0];
    const float* feat = (const float*)d_in[1];
    if (n_in >= 2 && in_sizes[0] > in_sizes[1]) {   // defensive: xyz is smaller
        const float* tmp = xyz; xyz = feat; feat = tmp;
    }
    float* out = (float*)d_out;

    const int fps_smem = N_PTS * 4;     // min_d
    cudaFuncSetAttribute(fps_kernel, cudaFuncAttributeMaxDynamicSharedMemorySize,
                         fps_smem);

    sort_kernel<<<B_SZ, 1024>>>(xyz);
    fps_kernel<<<B_SZ, FPS_T, fps_smem>>>(xyz, out);
    group_kernel<<<(B_SZ * S_SAMPLES) / BQ_WARPS, BQ_WARPS * 32>>>(xyz, feat, out);
}